// round 15
// baseline (speedup 1.0000x reference)
#include <cuda_runtime.h>
#include <cuda_fp16.h>
#include <cstdint>
#include <math.h>

// Problem: B=4096, IN=784, H=256, OUT=10, TOL=1e-3, MAX_ITERS=200
#define NB 4096
#define NIN 784
#define NH 256
#define NOUT 10
#define TOLV 1e-3f
#define MAXIT 200

#define ROWS 32
#define NCTA (NB / ROWS)                 // 128 CTAs <= 148 SMs -> co-resident
#define TPB 256                          // 8 warps
#define NW 8

// ---- iteration-phase SMEM layout (int8) ----
#define WQ_STRIDE 272                    // 256B row + 16B pad
#define AS0_OFF 69632
#define AS1_OFF 78336
#define SW0_OFF 87040
#define SW1_OFF 88064
#define REM_OFF 89088

// ---- xproj int8 SMEM layout (K padded 784->832, 13 chunks of 64; stride 80B) ----
#define KCH8 64
#define NCH8 13
#define X8_STR 80
#define XB8H0 0
#define XB8L0 20480
#define XB8H1 40960
#define XB8L1 61440
#define XA8H0 81920
#define XA8L0 84480
#define XA8H1 87040
#define XA8L1 89600
#define SMEM_SZ 92160

// ---------------- device scratch ----------------
__device__ __align__(16) signed char g_Wq8[NH * NH];        // int8 round(tanh(W)*255)
__device__ float g_ab[2];                                    // alpha, beta
__device__ float g_add[NH];                                  // b_ip + bq
__device__ __align__(16) signed char g_Wh8[NCH8 * NH * KCH8]; // W_ip digit1 (x3500), [kc][n][64]
__device__ __align__(16) signed char g_Wl8[NCH8 * NH * KCH8]; // W_ip digit2 (x896000)
__device__ unsigned g_bar[4];
__device__ unsigned g_T;

// ---------------- helpers ----------------
__device__ __forceinline__ uint32_t smem_u32(const void* p) {
    uint32_t r;
    asm("{ .reg .u64 t; cvta.to.shared.u64 t, %1; cvt.u32.u64 %0, t; }" : "=r"(r) : "l"(p));
    return r;
}
__device__ __forceinline__ void ldsm_x4(uint32_t a, uint32_t& r0, uint32_t& r1,
                                        uint32_t& r2, uint32_t& r3) {
    asm volatile("ldmatrix.sync.aligned.m8n8.x4.shared.b16 {%0,%1,%2,%3}, [%4];"
                 : "=r"(r0), "=r"(r1), "=r"(r2), "=r"(r3) : "r"(a));
}
__device__ __forceinline__ void imma(int* c, const uint32_t* a, uint32_t b0, uint32_t b1) {
    asm volatile("mma.sync.aligned.m16n8k32.row.col.s32.s8.s8.s32 "
                 "{%0,%1,%2,%3}, {%4,%5,%6,%7}, {%8,%9}, {%0,%1,%2,%3};"
                 : "+r"(c[0]), "+r"(c[1]), "+r"(c[2]), "+r"(c[3])
                 : "r"(a[0]), "r"(a[1]), "r"(a[2]), "r"(a[3]), "r"(b0), "r"(b1));
}
__device__ __forceinline__ void cp16(uint32_t dst, const void* src) {
    asm volatile("cp.async.cg.shared.global [%0], [%1], 16;" :: "r"(dst), "l"(src));
}
#define CP_COMMIT() asm volatile("cp.async.commit_group;" ::: "memory")
#define CP_WAIT0()  asm volatile("cp.async.wait_group 0;" ::: "memory")

// tanh(s)*127 -> packed 2x int8 (low 2 bytes of result), via MUFU f16x2
__device__ __forceinline__ unsigned qtanh2(float s0, float s1) {
    uint32_t p2;
    asm("cvt.rn.f16x2.f32 %0, %1, %2;" : "=r"(p2) : "f"(s1), "f"(s0));
    asm("tanh.approx.f16x2 %0, %1;" : "=r"(p2) : "r"(p2));
    asm("mul.f16x2 %0, %1, %2;" : "=r"(p2) : "r"(p2), "r"(0x57F057F0u));  // *127 (f16 0x57F0)
    unsigned short hlo, hhi;
    asm("mov.b32 {%0,%1}, %2;" : "=h"(hlo), "=h"(hhi) : "r"(p2));
    short i0, i1;
    asm("cvt.rni.s16.f16 %0, %1;" : "=h"(i0) : "h"(hlo));
    asm("cvt.rni.s16.f16 %0, %1;" : "=h"(i1) : "h"(hhi));
    return __byte_perm((unsigned)(unsigned short)i0, (unsigned)(unsigned short)i1, 0x0040);
}

// ---------------- K0: fused setup ----------------
__global__ void k_setup(const float* __restrict__ W_raw, const float* __restrict__ b_raw,
                        const float* __restrict__ a_raw, const float* __restrict__ be_raw,
                        const float* __restrict__ b_ip, const float* __restrict__ W_ip) {
    int b = blockIdx.x, t = threadIdx.x;
    if (b < NH) {                                   // Wq row b -> int8
        float w = W_raw[b * NH + t];
        float q = rintf(tanhf(w) * 255.0f);
        q = fminf(fmaxf(q, -127.0f), 127.0f);       // data range is +-2; int8-safe clamp
        g_Wq8[b * NH + t] = (signed char)(int)q;
    } else if (b == NH) {
        float bb = b_raw[t];
        float q = rintf(tanhf(bb) * 255.0f);
        q = fminf(fmaxf(q, -256.0f), 255.0f);
        g_add[t] = b_ip[t] + q / 255.0f;
        if (t < 4) g_bar[t] = 0u;
        if (t == 0) {
            g_T = 0u;
            g_ab[0] = 1.0f / (1.0f + expf(-a_raw[0]));
            g_ab[1] = 1.0f / (1.0f + expf(-be_raw[0]));
        }
    } else {                                        // W_ip row: 2-digit int8 split
        int n = b - NH - 1;
        for (int k = t; k < NCH8 * KCH8; k += blockDim.x) {
            float v = (k < NIN) ? W_ip[n * NIN + k] : 0.0f;
            float f1 = rintf(fminf(fmaxf(v * 3500.0f, -127.0f), 127.0f));
            float rr = fmaf(f1, -(1.0f / 3500.0f), v);
            float f2 = rintf(fminf(fmaxf(rr * 896000.0f, -127.0f), 127.0f));
            int kc = k >> 6, kk = k & 63;
            int dst = kc * (NH * KCH8) + n * KCH8 + kk;
            g_Wh8[dst] = (signed char)(int)f1;
            g_Wl8[dst] = (signed char)(int)f2;
        }
    }
}

// ---------------- K1: fused int8 xproj + two-phase INT8 iteration + output GEMM --------
__global__ void __launch_bounds__(TPB, 1) k_main(const float* __restrict__ x,
                                                 const float* __restrict__ Wop,
                                                 const float* __restrict__ bop,
                                                 float* __restrict__ out) {
    extern __shared__ char smem[];
    const uint32_t sbase = smem_u32(smem);
    const int tid = threadIdx.x;
    const int w = tid >> 5, l = tid & 31;
    const int r0 = l >> 2, c0 = (l & 3) * 2;
    const int colBase = w * 32;
    const int row0 = blockIdx.x * ROWS;
    unsigned* sRem = (unsigned*)(smem + REM_OFF);

    // ================= xproj: 2-digit int8 IMMA, cp.async double-buffered ===============
    // c = [acc_hh]/56000 + [acc_hl + acc_lh]/14336000 + (b_ip + bq)
    float cR[2][4][4];
    {
        int acc1[2][4][4], acc2[2][4][4];
#pragma unroll
        for (int mt = 0; mt < 2; ++mt)
#pragma unroll
            for (int nt = 0; nt < 4; ++nt)
#pragma unroll
                for (int e = 0; e < 4; ++e) { acc1[mt][nt][e] = 0; acc2[mt][nt][e] = 0; }

        const uint32_t aP = (uint32_t)((l & 15) * X8_STR + ((l >> 4) * 16));
        const uint32_t bP = (uint32_t)((colBase + (l & 15)) * X8_STR + ((l >> 4) * 16));
        const int xr = tid >> 3, xk0 = (tid & 7) * 8;
        float xv8[8];

        auto issueB = [&](int kc) {
            const int bb = kc & 1;
            const char* sH = (const char*)g_Wh8 + kc * (NH * KCH8);
            const char* sL = (const char*)g_Wl8 + kc * (NH * KCH8);
            const uint32_t dh = sbase + (bb ? XB8H1 : XB8H0);
            const uint32_t dl = sbase + (bb ? XB8L1 : XB8L0);
#pragma unroll
            for (int j = 0; j < 4; ++j) {
                int idx = tid + j * 256;                      // 1024 16B pieces / digit
                int n = idx >> 2, p = idx & 3;
                uint32_t d = (uint32_t)(n * X8_STR + p * 16);
                cp16(dh + d, sH + idx * 16);
                cp16(dl + d, sL + idx * 16);
            }
            CP_COMMIT();
        };
        auto loadX = [&](int kc) {
#pragma unroll
            for (int j = 0; j < 8; ++j) {
                int gk = kc * KCH8 + xk0 + j;
                xv8[j] = (gk < NIN) ? x[(row0 + xr) * NIN + gk] : 0.0f;
            }
        };
        auto stageA = [&](int buf) {
            char* pH = smem + (buf ? XA8H1 : XA8H0) + xr * X8_STR + xk0;
            char* pL = smem + (buf ? XA8L1 : XA8L0) + xr * X8_STR + xk0;
            uint32_t d1[2] = {0u, 0u}, d2[2] = {0u, 0u};
#pragma unroll
            for (int j = 0; j < 8; ++j) {
                float v = xv8[j];
                float f1 = rintf(fminf(fmaxf(v * 16.0f, -127.0f), 127.0f));
                float rr = fmaf(f1, -0.0625f, v);
                float f2 = rintf(fminf(fmaxf(rr * 4096.0f, -127.0f), 127.0f));
                d1[j >> 2] |= ((uint32_t)(int)f1 & 255u) << ((j & 3) * 8);
                d2[j >> 2] |= ((uint32_t)(int)f2 & 255u) << ((j & 3) * 8);
            }
            *(uint2*)pH = make_uint2(d1[0], d1[1]);
            *(uint2*)pL = make_uint2(d2[0], d2[1]);
        };

        // prologue
        issueB(0);
        loadX(0);
        stageA(0);
        CP_WAIT0();

#pragma unroll 1
        for (int kc = 0; kc < NCH8; ++kc) {
            __syncthreads();                          // chunk kc visible; other buffer free
            const int cb = kc & 1;
            if (kc + 1 < NCH8) { issueB(kc + 1); loadX(kc + 1); }

            const uint32_t ah = sbase + (cb ? XA8H1 : XA8H0) + aP;
            const uint32_t al = sbase + (cb ? XA8L1 : XA8L0) + aP;
            const uint32_t bh = sbase + (cb ? XB8H1 : XB8H0) + bP;
            const uint32_t bl = sbase + (cb ? XB8L1 : XB8L0) + bP;
#pragma unroll
            for (int ks = 0; ks < 2; ++ks) {
                const uint32_t kb = (uint32_t)(ks * 32);
                uint32_t A1[2][4], A2[2][4], B1[2][4], B2[2][4];
#pragma unroll
                for (int mt = 0; mt < 2; ++mt) {
                    ldsm_x4(ah + (uint32_t)(mt * 16 * X8_STR) + kb,
                            A1[mt][0], A1[mt][1], A1[mt][2], A1[mt][3]);
                    ldsm_x4(al + (uint32_t)(mt * 16 * X8_STR) + kb,
                            A2[mt][0], A2[mt][1], A2[mt][2], A2[mt][3]);
                }
#pragma unroll
                for (int np = 0; np < 2; ++np) {
                    ldsm_x4(bh + (uint32_t)(np * 16 * X8_STR) + kb,
                            B1[np][0], B1[np][1], B1[np][2], B1[np][3]);
                    ldsm_x4(bl + (uint32_t)(np * 16 * X8_STR) + kb,
                            B2[np][0], B2[np][1], B2[np][2], B2[np][3]);
                }
#pragma unroll
                for (int mt = 0; mt < 2; ++mt)
#pragma unroll
                    for (int nt = 0; nt < 4; ++nt) {
                        uint32_t h0 = B1[nt >> 1][nt & 1], h1 = B1[nt >> 1][(nt & 1) + 2];
                        uint32_t q0 = B2[nt >> 1][nt & 1], q1 = B2[nt >> 1][(nt & 1) + 2];
                        imma(acc1[mt][nt], A1[mt], h0, h1);
                        imma(acc2[mt][nt], A1[mt], q0, q1);
                        imma(acc2[mt][nt], A2[mt], h0, h1);
                    }
            }

            if (kc + 1 < NCH8) { stageA((kc + 1) & 1); CP_WAIT0(); }
        }

        // decode: cR = acc1/56000 + acc2/14336000 + (b_ip + bq)
        const float K1 = 1.0f / 56000.0f;
        const float K2 = 1.0f / 14336000.0f;
#pragma unroll
        for (int nt = 0; nt < 4; ++nt) {
            int col = colBase + nt * 8 + c0;
            float a0 = g_add[col], a1 = g_add[col + 1];
#pragma unroll
            for (int mt = 0; mt < 2; ++mt)
#pragma unroll
                for (int ep = 0; ep < 2; ++ep) {
                    cR[mt][nt][ep * 2 + 0] = fmaf((float)acc1[mt][nt][ep * 2 + 0], K1,
                                             fmaf((float)acc2[mt][nt][ep * 2 + 0], K2, a0));
                    cR[mt][nt][ep * 2 + 1] = fmaf((float)acc1[mt][nt][ep * 2 + 1], K1,
                                             fmaf((float)acc2[mt][nt][ep * 2 + 1], K2, a1));
                }
        }
    }
    float s[2][4][4];
#pragma unroll
    for (int mt = 0; mt < 2; ++mt)
#pragma unroll
        for (int nt = 0; nt < 4; ++nt)
#pragma unroll
            for (int e = 0; e < 4; ++e) s[mt][nt][e] = cR[mt][nt][e];

    // ================= stage Wq int8 into padded SMEM =================
    __syncthreads();
    {
        const int4* src = (const int4*)g_Wq8;
        for (int i = tid; i < NH * 16; i += TPB) {
            int n = i >> 4, p = i & 15;
            *(int4*)(smem + n * WQ_STRIDE + p * 16) = src[i];
        }
    }
    const float alpha = g_ab[0];
    const float betaI = g_ab[1] * (1.0f / (255.0f * 127.0f));
    __syncthreads();

    const uint32_t aPieceI = (uint32_t)((l & 15) * WQ_STRIDE + ((l >> 4) * 16));
    const uint32_t aAddr0 = sbase + AS0_OFF + aPieceI;
    const uint32_t aAddr1 = sbase + AS1_OFF + aPieceI;
    const uint32_t bAddrW = sbase + (uint32_t)((colBase + (l & 15)) * WQ_STRIDE + (l >> 4) * 16);

    uint32_t bR[8][2][4];
#pragma unroll
    for (int ks = 0; ks < 8; ++ks)
#pragma unroll
        for (int np = 0; np < 2; ++np)
            ldsm_x4(bAddrW + (uint32_t)(np * 16 * WQ_STRIDE) + (uint32_t)(ks * 32),
                    bR[ks][np][0], bR[ks][np][1], bR[ks][np][2], bR[ks][np][3]);

    unsigned sticky = 0u;
    int done_it = MAXIT;

    // ============ PHASE 1: local convergence, 1 sync/iter (delayed vote, dbl-buffer) ====
#pragma unroll 1
    for (int it = 0; it < MAXIT; ++it) {
        const uint32_t sbuf = (it & 1) ? AS1_OFF : AS0_OFF;
        const uint32_t abase = (it & 1) ? aAddr1 : aAddr0;
#pragma unroll
        for (int mt = 0; mt < 2; ++mt)
#pragma unroll
            for (int nt = 0; nt < 4; ++nt)
#pragma unroll
                for (int ep = 0; ep < 2; ++ep) {
                    unsigned pk = qtanh2(s[mt][nt][ep * 2 + 0], s[mt][nt][ep * 2 + 1]);
                    int row = mt * 16 + r0 + 8 * ep;
                    int col = colBase + nt * 8 + c0;
                    *(unsigned short*)(smem + sbuf + row * WQ_STRIDE + col) = (unsigned short)pk;
                }
        __syncthreads();

        if (it > 0) {
            const float* sv = (const float*)(smem + ((it & 1) ? SW0_OFF : SW1_OFF));
            float m = sv[l];
#pragma unroll
            for (int ww = 1; ww < NW; ++ww)
                m = fmaxf(m, sv[ww * 32 + l]);
            sticky |= __ballot_sync(0xFFFFFFFFu, m < TOLV);
            if (sticky == 0xFFFFFFFFu) { done_it = it; break; }
        }

        int acc[2][4][4];
#pragma unroll
        for (int mt = 0; mt < 2; ++mt)
#pragma unroll
            for (int nt = 0; nt < 4; ++nt)
#pragma unroll
                for (int e = 0; e < 4; ++e) acc[mt][nt][e] = 0;
#pragma unroll
        for (int ks = 0; ks < 8; ++ks) {
            uint32_t aF[2][4];
#pragma unroll
            for (int mt = 0; mt < 2; ++mt)
                ldsm_x4(abase + (uint32_t)(mt * 16 * WQ_STRIDE) + (uint32_t)(ks * 32),
                        aF[mt][0], aF[mt][1], aF[mt][2], aF[mt][3]);
#pragma unroll
            for (int mt = 0; mt < 2; ++mt)
#pragma unroll
                for (int nt = 0; nt < 4; ++nt)
                    imma(acc[mt][nt], aF[mt],
                         bR[ks][nt >> 1][nt & 1], bR[ks][nt >> 1][(nt & 1) + 2]);
        }

        float dmax[4] = {0.0f, 0.0f, 0.0f, 0.0f};
#pragma unroll
        for (int mt = 0; mt < 2; ++mt)
#pragma unroll
            for (int nt = 0; nt < 4; ++nt)
#pragma unroll
                for (int e = 0; e < 4; ++e) {
                    float sv = s[mt][nt][e];
                    float sn = fmaf(alpha, sv,
                                    fmaf(betaI, (float)acc[mt][nt][e], cR[mt][nt][e]));
                    int j = mt * 2 + (e >> 1);
                    dmax[j] = fmaxf(dmax[j], fabsf(sn - sv));
                    s[mt][nt][e] = sn;
                }
#pragma unroll
        for (int off = 1; off <= 2; off <<= 1)
#pragma unroll
            for (int j = 0; j < 4; ++j)
                dmax[j] = fmaxf(dmax[j], __shfl_xor_sync(0xFFFFFFFFu, dmax[j], off));
        float* sw = (float*)(smem + ((it & 1) ? SW1_OFF : SW0_OFF));
        if ((l & 3) == 0) {
#pragma unroll
            for (int j = 0; j < 4; ++j)
                sw[w * 32 + r0 + 8 * j] = dmax[j];
        }
    }

    // ================= single grid barrier: T = max(t_local) =================
    if (tid == 0) {
        atomicMax(&g_T, (unsigned)done_it);
        __threadfence();
        atomicAdd(&g_bar[0], 1u);
        unsigned vv;
        do {
            asm volatile("ld.acquire.gpu.u32 %0, [%1];" : "=r"(vv) : "l"(&g_bar[0]) : "memory");
        } while (vv < (unsigned)NCTA);
        unsigned tg;
        asm volatile("ld.acquire.gpu.u32 %0, [%1];" : "=r"(tg) : "l"(&g_T) : "memory");
        *sRem = tg;
    }
    __syncthreads();
    const int rem = (int)*sRem - done_it;

    // ================= PHASE 2: counted tail, 1 sync/iter =================
#pragma unroll 1
    for (int i = 0; i < rem; ++i) {
        const uint32_t abase = (i & 1) ? aAddr1 : aAddr0;
        const uint32_t sbuf = (i & 1) ? AS1_OFF : AS0_OFF;
#pragma unroll
        for (int mt = 0; mt < 2; ++mt)
#pragma unroll
            for (int nt = 0; nt < 4; ++nt)
#pragma unroll
                for (int ep = 0; ep < 2; ++ep) {
                    unsigned pk = qtanh2(s[mt][nt][ep * 2 + 0], s[mt][nt][ep * 2 + 1]);
                    int row = mt * 16 + r0 + 8 * ep;
                    int col = colBase + nt * 8 + c0;
                    *(unsigned short*)(smem + sbuf + row * WQ_STRIDE + col) = (unsigned short)pk;
                }
        __syncthreads();

        int acc[2][4][4];
#pragma unroll
        for (int mt = 0; mt < 2; ++mt)
#pragma unroll
            for (int nt = 0; nt < 4; ++nt)
#pragma unroll
                for (int e = 0; e < 4; ++e) acc[mt][nt][e] = 0;
#pragma unroll
        for (int ks = 0; ks < 8; ++ks) {
            uint32_t aF[2][4];
#pragma unroll
            for (int mt = 0; mt < 2; ++mt)
                ldsm_x4(abase + (uint32_t)(mt * 16 * WQ_STRIDE) + (uint32_t)(ks * 32),
                        aF[mt][0], aF[mt][1], aF[mt][2], aF[mt][3]);
#pragma unroll
            for (int mt = 0; mt < 2; ++mt)
#pragma unroll
                for (int nt = 0; nt < 4; ++nt)
                    imma(acc[mt][nt], aF[mt],
                         bR[ks][nt >> 1][nt & 1], bR[ks][nt >> 1][(nt & 1) + 2]);
        }
#pragma unroll
        for (int mt = 0; mt < 2; ++mt)
#pragma unroll
            for (int nt = 0; nt < 4; ++nt)
#pragma unroll
                for (int e = 0; e < 4; ++e)
                    s[mt][nt][e] = fmaf(alpha, s[mt][nt][e],
                                        fmaf(betaI, (float)acc[mt][nt][e], cR[mt][nt][e]));
    }

    // ================= epilogue: out = s @ Wop^T + bop =================
    __syncthreads();
    float* wopS = (float*)smem;
    float* partS = (float*)(smem + 10240);
    for (int i = tid; i < NOUT * NH; i += TPB) wopS[i] = Wop[i];
    __syncthreads();
    float part[4][NOUT];
#pragma unroll
    for (int j = 0; j < 4; ++j) {
#pragma unroll
        for (int o = 0; o < NOUT; ++o) part[j][o] = 0.0f;
        int mt = j >> 1, eb = (j & 1) * 2;
#pragma unroll
        for (int nt = 0; nt < 4; ++nt)
#pragma unroll
            for (int b = 0; b < 2; ++b) {
                float sv = s[mt][nt][eb + b];
                int col = colBase + nt * 8 + c0 + b;
#pragma unroll
                for (int o = 0; o < NOUT; ++o)
                    part[j][o] = fmaf(sv, wopS[o * NH + col], part[j][o]);
            }
    }
#pragma unroll
    for (int off = 1; off <= 2; off <<= 1)
#pragma unroll
        for (int j = 0; j < 4; ++j)
#pragma unroll
            for (int o = 0; o < NOUT; ++o)
                part[j][o] += __shfl_xor_sync(0xFFFFFFFFu, part[j][o], off);
    if ((l & 3) == 0) {
#pragma unroll
        for (int j = 0; j < 4; ++j)
#pragma unroll
            for (int o = 0; o < NOUT; ++o)
                partS[((r0 + 8 * j) * NW + w) * NOUT + o] = part[j][o];
    }
    __syncthreads();
    for (int i = tid; i < ROWS * NOUT; i += TPB) {
        int row = i / NOUT, o = i % NOUT;
        float v = bop[o];
#pragma unroll
        for (int ww = 0; ww < NW; ++ww)
            v += partS[(row * NW + ww) * NOUT + o];
        out[(row0 + row) * NOUT + o] = v;
    }
}

// ---------------- launch ----------------
extern "C" void kernel_launch(void* const* d_in, const int* in_sizes, int n_in,
                              void* d_out, int out_size) {
    const float *x = nullptr, *W_ip = nullptr, *b_ip = nullptr, *W_op = nullptr,
                *b_op = nullptr, *W_raw = nullptr, *b_raw = nullptr,
                *a_raw = nullptr, *be_raw = nullptr;
    for (int i = 0; i < n_in; ++i) {
        const float* p = (const float*)d_in[i];
        switch (in_sizes[i]) {
            case NB * NIN:  x = p; break;
            case NH * NIN:  W_ip = p; break;
            case NH * NH:   W_raw = p; break;
            case NOUT * NH: W_op = p; break;
            case NOUT:      b_op = p; break;
            case NH:        if (!b_ip) b_ip = p; else b_raw = p; break;
            case 1:         if (!a_raw) a_raw = p; else be_raw = p; break;
            default: break;
        }
    }

    cudaFuncSetAttribute(k_main, cudaFuncAttributeMaxDynamicSharedMemorySize, SMEM_SZ);

    k_setup<<<2 * NH + 1, 256>>>(W_raw, b_raw, a_raw, be_raw, b_ip, W_ip);
    k_main<<<NCTA, TPB, SMEM_SZ>>>(x, W_op, b_op, (float*)d_out);
}

// round 16
// speedup vs baseline: 1.0621x; 1.0621x over previous
#include <cuda_runtime.h>
#include <cuda_fp16.h>
#include <cstdint>
#include <math.h>

// Problem: B=4096, IN=784, H=256, OUT=10, TOL=1e-3, MAX_ITERS=200
#define NB 4096
#define NIN 784
#define NH 256
#define NOUT 10
#define TOLV 1e-3f
#define MAXIT 200

#define ROWS 32
#define NCTA (NB / ROWS)                 // 128 CTAs <= 148 SMs -> co-resident
#define TPB 256                          // 8 warps
#define NW 8

// ---- iteration-phase SMEM layout (int8) ----
#define WQ_STRIDE 272                    // 256B row + 16B pad
#define AS0_OFF 69632
#define AS1_OFF 78336
#define SW0_OFF 87040
#define SW1_OFF 88064
#define REM_OFF 89088

// ---- xproj SMEM layout (K padded 784->800, 10 chunks of 80; stride 176B) ----
#define KPAD 800
#define KCH 80
#define NCH 10
#define XB_STR 176
#define XBH0 0
#define XBH1 45056
#define XAH0 90112
#define XAL0 95744
#define XAH1 101376
#define XAL1 107008
#define SMEM_SZ 112640

// ---------------- device scratch ----------------
__device__ __align__(16) signed char g_Wq8[NH * NH];  // int8 round(tanh(W)*255)
__device__ float g_ab[2];                             // alpha, beta
__device__ float g_add[NH];                           // b_ip + bq
__device__ __align__(16) __half g_Wh[KPAD * NH];      // W_ip fp16, [kc][n][80], zero-padded
__device__ unsigned g_bar[4];
__device__ unsigned g_T;

// ---------------- helpers ----------------
__device__ __forceinline__ uint32_t smem_u32(const void* p) {
    uint32_t r;
    asm("{ .reg .u64 t; cvta.to.shared.u64 t, %1; cvt.u32.u64 %0, t; }" : "=r"(r) : "l"(p));
    return r;
}
__device__ __forceinline__ void ldsm_x4(uint32_t a, uint32_t& r0, uint32_t& r1,
                                        uint32_t& r2, uint32_t& r3) {
    asm volatile("ldmatrix.sync.aligned.m8n8.x4.shared.b16 {%0,%1,%2,%3}, [%4];"
                 : "=r"(r0), "=r"(r1), "=r"(r2), "=r"(r3) : "r"(a));
}
__device__ __forceinline__ void hmma(float* c, const uint32_t* a, const uint32_t* b) {
    asm volatile("mma.sync.aligned.m16n8k16.row.col.f32.f16.f16.f32 "
                 "{%0,%1,%2,%3}, {%4,%5,%6,%7}, {%8,%9}, {%0,%1,%2,%3};"
                 : "+f"(c[0]), "+f"(c[1]), "+f"(c[2]), "+f"(c[3])
                 : "r"(a[0]), "r"(a[1]), "r"(a[2]), "r"(a[3]), "r"(b[0]), "r"(b[1]));
}
__device__ __forceinline__ void imma(int* c, const uint32_t* a, uint32_t b0, uint32_t b1) {
    asm volatile("mma.sync.aligned.m16n8k32.row.col.s32.s8.s8.s32 "
                 "{%0,%1,%2,%3}, {%4,%5,%6,%7}, {%8,%9}, {%0,%1,%2,%3};"
                 : "+r"(c[0]), "+r"(c[1]), "+r"(c[2]), "+r"(c[3])
                 : "r"(a[0]), "r"(a[1]), "r"(a[2]), "r"(a[3]), "r"(b0), "r"(b1));
}
__device__ __forceinline__ void cp16(uint32_t dst, const void* src) {
    asm volatile("cp.async.cg.shared.global [%0], [%1], 16;" :: "r"(dst), "l"(src));
}
#define CP_COMMIT() asm volatile("cp.async.commit_group;" ::: "memory")
#define CP_WAIT0()  asm volatile("cp.async.wait_group 0;" ::: "memory")
__device__ __forceinline__ uint32_t pack_h2(__half a, __half b) {
    return (uint32_t)__half_as_ushort(a) | ((uint32_t)__half_as_ushort(b) << 16);
}
// tanh(s)*127 -> packed 2x int8 (low 2 bytes), via MUFU f16x2 (validated R15)
__device__ __forceinline__ unsigned qtanh2(float s0, float s1) {
    uint32_t p2;
    asm("cvt.rn.f16x2.f32 %0, %1, %2;" : "=r"(p2) : "f"(s1), "f"(s0));
    asm("tanh.approx.f16x2 %0, %1;" : "=r"(p2) : "r"(p2));
    asm("mul.f16x2 %0, %1, %2;" : "=r"(p2) : "r"(p2), "r"(0x57F057F0u));  // *127
    unsigned short hlo, hhi;
    asm("mov.b32 {%0,%1}, %2;" : "=h"(hlo), "=h"(hhi) : "r"(p2));
    short i0, i1;
    asm("cvt.rni.s16.f16 %0, %1;" : "=h"(i0) : "h"(hlo));
    asm("cvt.rni.s16.f16 %0, %1;" : "=h"(i1) : "h"(hhi));
    return __byte_perm((unsigned)(unsigned short)i0, (unsigned)(unsigned short)i1, 0x0040);
}

// ---------------- K0: fused setup ----------------
__global__ void k_setup(const float* __restrict__ W_raw, const float* __restrict__ b_raw,
                        const float* __restrict__ a_raw, const float* __restrict__ be_raw,
                        const float* __restrict__ b_ip, const float* __restrict__ W_ip) {
    int b = blockIdx.x, t = threadIdx.x;
    if (b < NH) {                                   // Wq row b -> int8
        float w = W_raw[b * NH + t];
        float q = rintf(tanhf(w) * 255.0f);
        q = fminf(fmaxf(q, -127.0f), 127.0f);       // data range is +-2; int8-safe clamp
        g_Wq8[b * NH + t] = (signed char)(int)q;
    } else if (b == NH) {
        float bb = b_raw[t];
        float q = rintf(tanhf(bb) * 255.0f);
        q = fminf(fmaxf(q, -256.0f), 255.0f);
        g_add[t] = b_ip[t] + q / 255.0f;
        if (t < 4) g_bar[t] = 0u;
        if (t == 0) {
            g_T = 0u;
            g_ab[0] = 1.0f / (1.0f + expf(-a_raw[0]));
            g_ab[1] = 1.0f / (1.0f + expf(-be_raw[0]));
        }
    } else {                                        // W_ip row: fp16 hi only (Wl dropped)
        int n = b - NH - 1;
        for (int k2 = t; k2 < KPAD / 2; k2 += blockDim.x) {
            int k = 2 * k2;
            float v0 = (k < NIN) ? W_ip[n * NIN + k] : 0.0f;
            float v1 = (k + 1 < NIN) ? W_ip[n * NIN + k + 1] : 0.0f;
            __half h0 = __float2half_rn(v0), h1 = __float2half_rn(v1);
            int kc = k / KCH, kk = k % KCH;
            int dst = kc * (NH * KCH) + n * KCH + kk;
            *(__half2*)&g_Wh[dst] = __halves2half2(h0, h1);
        }
    }
}

// ---------------- K1: fused xproj + two-phase INT8 iteration + output GEMM --------------
__global__ void __launch_bounds__(TPB, 1) k_main(const float* __restrict__ x,
                                                 const float* __restrict__ Wop,
                                                 const float* __restrict__ bop,
                                                 float* __restrict__ out) {
    extern __shared__ char smem[];
    const uint32_t sbase = smem_u32(smem);
    const int tid = threadIdx.x;
    const int w = tid >> 5, l = tid & 31;
    const int r0 = l >> 2, c0 = (l & 3) * 2;
    const int colBase = w * 32;
    const int row0 = blockIdx.x * ROWS;
    unsigned* sRem = (unsigned*)(smem + REM_OFF);

    // ================= xproj: c = (xh+xl) @ Wh^T + add (cp.async double-buffered) =======
    float cR[2][4][4];
#pragma unroll
    for (int mt = 0; mt < 2; ++mt)
#pragma unroll
        for (int nt = 0; nt < 4; ++nt)
#pragma unroll
            for (int e = 0; e < 4; ++e) cR[mt][nt][e] = 0.0f;
    {
        const uint32_t aPiece = (uint32_t)((l & 15) * XB_STR + (l & 16));
        const uint32_t bPiece = (uint32_t)(((l & 7) + ((l & 16) >> 1)) * XB_STR + (l & 8) * 2);
        const int xr = tid >> 3, xk0 = (tid & 7) * 10;
        float2 xv[5];

        // -- prologue: B0 via cp.async, A0 staged directly --
        {
            const char* srcH = (const char*)g_Wh;
#pragma unroll
            for (int j = 0; j < 10; ++j) {
                int idx = tid + j * 256;                      // 2560 16B pieces
                int n = idx / 10, p = idx - n * 10;
                cp16(sbase + XBH0 + (uint32_t)(n * XB_STR + p * 16), srcH + idx * 16);
            }
            CP_COMMIT();
#pragma unroll
            for (int p = 0; p < 5; ++p) {
                int gk = xk0 + 2 * p;
                xv[p] = (gk < NIN) ? *(const float2*)&x[(row0 + xr) * NIN + gk]
                                   : make_float2(0.f, 0.f);
            }
            char* pH = smem + XAH0 + xr * XB_STR + xk0 * 2;
            char* pL = smem + XAL0 + xr * XB_STR + xk0 * 2;
#pragma unroll
            for (int p = 0; p < 5; ++p) {
                __half h0 = __float2half_rn(xv[p].x), h1 = __float2half_rn(xv[p].y);
                __half l0 = __float2half_rn(xv[p].x - __half2float(h0));
                __half l1 = __float2half_rn(xv[p].y - __half2float(h1));
                *(uint32_t*)(pH + 4 * p) = pack_h2(h0, h1);
                *(uint32_t*)(pL + 4 * p) = pack_h2(l0, l1);
            }
            CP_WAIT0();
        }

#pragma unroll 1
        for (int kc = 0; kc < NCH; ++kc) {
            __syncthreads();                              // chunk kc visible; old bufs free
            const int cb = kc & 1, nb = (kc + 1) & 1;
            if (kc + 1 < NCH) {
                const char* srcH = (const char*)g_Wh + (kc + 1) * (NH * KCH * 2);
                const uint32_t bh = sbase + (nb ? XBH1 : XBH0);
#pragma unroll
                for (int j = 0; j < 10; ++j) {
                    int idx = tid + j * 256;
                    int n = idx / 10, p = idx - n * 10;
                    cp16(bh + (uint32_t)(n * XB_STR + p * 16), srcH + idx * 16);
                }
                CP_COMMIT();
#pragma unroll
                for (int p = 0; p < 5; ++p) {
                    int gk = (kc + 1) * KCH + xk0 + 2 * p;
                    xv[p] = (gk < NIN) ? *(const float2*)&x[(row0 + xr) * NIN + gk]
                                       : make_float2(0.f, 0.f);
                }
            }

            // MMA over chunk kc (5 k16-steps): xh@Wh + xl@Wh
            const uint32_t aH = sbase + (cb ? XAH1 : XAH0) + aPiece;
            const uint32_t aL = sbase + (cb ? XAL1 : XAL0) + aPiece;
            const uint32_t bH = sbase + (cb ? XBH1 : XBH0) + bPiece;
#pragma unroll
            for (int ks = 0; ks < 5; ++ks) {
                const uint32_t kb = (uint32_t)(ks * 32);
                uint32_t aHf[2][4], aLf[2][4], bHf[2][4];
#pragma unroll
                for (int mt = 0; mt < 2; ++mt) {
                    ldsm_x4(aH + (uint32_t)(mt * 16 * XB_STR) + kb,
                            aHf[mt][0], aHf[mt][1], aHf[mt][2], aHf[mt][3]);
                    ldsm_x4(aL + (uint32_t)(mt * 16 * XB_STR) + kb,
                            aLf[mt][0], aLf[mt][1], aLf[mt][2], aLf[mt][3]);
                }
#pragma unroll
                for (int np = 0; np < 2; ++np)
                    ldsm_x4(bH + (uint32_t)((colBase + np * 16) * XB_STR) + kb,
                            bHf[np][0], bHf[np][1], bHf[np][2], bHf[np][3]);
#pragma unroll
                for (int mt = 0; mt < 2; ++mt)
#pragma unroll
                    for (int nt = 0; nt < 4; ++nt) {
                        uint32_t* bh2 = &bHf[nt >> 1][(nt & 1) * 2];
                        hmma(cR[mt][nt], aHf[mt], bh2);
                        hmma(cR[mt][nt], aLf[mt], bh2);
                    }
            }

            if (kc + 1 < NCH) {
                char* pH = smem + (nb ? XAH1 : XAH0) + xr * XB_STR + xk0 * 2;
                char* pL = smem + (nb ? XAL1 : XAL0) + xr * XB_STR + xk0 * 2;
#pragma unroll
                for (int p = 0; p < 5; ++p) {
                    __half h0 = __float2half_rn(xv[p].x), h1 = __float2half_rn(xv[p].y);
                    __half l0 = __float2half_rn(xv[p].x - __half2float(h0));
                    __half l1 = __float2half_rn(xv[p].y - __half2float(h1));
                    *(uint32_t*)(pH + 4 * p) = pack_h2(h0, h1);
                    *(uint32_t*)(pL + 4 * p) = pack_h2(l0, l1);
                }
                CP_WAIT0();
            }
        }
#pragma unroll
        for (int nt = 0; nt < 4; ++nt) {
            int col = colBase + nt * 8 + c0;
            float a0 = g_add[col], a1 = g_add[col + 1];
#pragma unroll
            for (int mt = 0; mt < 2; ++mt)
#pragma unroll
                for (int ep = 0; ep < 2; ++ep) {
                    cR[mt][nt][ep * 2 + 0] += a0;
                    cR[mt][nt][ep * 2 + 1] += a1;
                }
        }
    }
    float s[2][4][4];
#pragma unroll
    for (int mt = 0; mt < 2; ++mt)
#pragma unroll
        for (int nt = 0; nt < 4; ++nt)
#pragma unroll
            for (int e = 0; e < 4; ++e) s[mt][nt][e] = cR[mt][nt][e];

    // ================= stage Wq int8 into padded SMEM =================
    __syncthreads();
    {
        const int4* src = (const int4*)g_Wq8;
        for (int i = tid; i < NH * 16; i += TPB) {
            int n = i >> 4, p = i & 15;
            *(int4*)(smem + n * WQ_STRIDE + p * 16) = src[i];
        }
    }
    const float alpha = g_ab[0];
    const float betaI = g_ab[1] * (1.0f / (255.0f * 127.0f));
    __syncthreads();

    const uint32_t aPieceI = (uint32_t)((l & 15) * WQ_STRIDE + ((l >> 4) * 16));
    const uint32_t aAddr0 = sbase + AS0_OFF + aPieceI;
    const uint32_t aAddr1 = sbase + AS1_OFF + aPieceI;
    const uint32_t bAddrW = sbase + (uint32_t)((colBase + (l & 15)) * WQ_STRIDE + (l >> 4) * 16);

    uint32_t bR[8][2][4];
#pragma unroll
    for (int ks = 0; ks < 8; ++ks)
#pragma unroll
        for (int np = 0; np < 2; ++np)
            ldsm_x4(bAddrW + (uint32_t)(np * 16 * WQ_STRIDE) + (uint32_t)(ks * 32),
                    bR[ks][np][0], bR[ks][np][1], bR[ks][np][2], bR[ks][np][3]);

    unsigned sticky = 0u;
    int done_it = MAXIT;

    // ============ PHASE 1: local convergence, 1 sync/iter (delayed vote, dbl-buffer) ====
#pragma unroll 1
    for (int it = 0; it < MAXIT; ++it) {
        const uint32_t sbuf = (it & 1) ? AS1_OFF : AS0_OFF;
        const uint32_t abase = (it & 1) ? aAddr1 : aAddr0;
#pragma unroll
        for (int mt = 0; mt < 2; ++mt)
#pragma unroll
            for (int nt = 0; nt < 4; ++nt)
#pragma unroll
                for (int ep = 0; ep < 2; ++ep) {
                    unsigned pk = qtanh2(s[mt][nt][ep * 2 + 0], s[mt][nt][ep * 2 + 1]);
                    int row = mt * 16 + r0 + 8 * ep;
                    int col = colBase + nt * 8 + c0;
                    *(unsigned short*)(smem + sbuf + row * WQ_STRIDE + col) = (unsigned short)pk;
                }
        __syncthreads();

        if (it > 0) {
            const float* sv = (const float*)(smem + ((it & 1) ? SW0_OFF : SW1_OFF));
            float m = sv[l];
#pragma unroll
            for (int ww = 1; ww < NW; ++ww)
                m = fmaxf(m, sv[ww * 32 + l]);
            sticky |= __ballot_sync(0xFFFFFFFFu, m < TOLV);
            if (sticky == 0xFFFFFFFFu) { done_it = it; break; }
        }

        int acc[2][4][4];
#pragma unroll
        for (int mt = 0; mt < 2; ++mt)
#pragma unroll
            for (int nt = 0; nt < 4; ++nt)
#pragma unroll
                for (int e = 0; e < 4; ++e) acc[mt][nt][e] = 0;
#pragma unroll
        for (int ks = 0; ks < 8; ++ks) {
            uint32_t aF[2][4];
#pragma unroll
            for (int mt = 0; mt < 2; ++mt)
                ldsm_x4(abase + (uint32_t)(mt * 16 * WQ_STRIDE) + (uint32_t)(ks * 32),
                        aF[mt][0], aF[mt][1], aF[mt][2], aF[mt][3]);
#pragma unroll
            for (int mt = 0; mt < 2; ++mt)
#pragma unroll
                for (int nt = 0; nt < 4; ++nt)
                    imma(acc[mt][nt], aF[mt],
                         bR[ks][nt >> 1][nt & 1], bR[ks][nt >> 1][(nt & 1) + 2]);
        }

        float dmax[4] = {0.0f, 0.0f, 0.0f, 0.0f};
#pragma unroll
        for (int mt = 0; mt < 2; ++mt)
#pragma unroll
            for (int nt = 0; nt < 4; ++nt)
#pragma unroll
                for (int e = 0; e < 4; ++e) {
                    float sv = s[mt][nt][e];
                    float sn = fmaf(alpha, sv,
                                    fmaf(betaI, (float)acc[mt][nt][e], cR[mt][nt][e]));
                    int j = mt * 2 + (e >> 1);
                    dmax[j] = fmaxf(dmax[j], fabsf(sn - sv));
                    s[mt][nt][e] = sn;
                }
#pragma unroll
        for (int off = 1; off <= 2; off <<= 1)
#pragma unroll
            for (int j = 0; j < 4; ++j)
                dmax[j] = fmaxf(dmax[j], __shfl_xor_sync(0xFFFFFFFFu, dmax[j], off));
        float* sw = (float*)(smem + ((it & 1) ? SW1_OFF : SW0_OFF));
        if ((l & 3) == 0) {
#pragma unroll
            for (int j = 0; j < 4; ++j)
                sw[w * 32 + r0 + 8 * j] = dmax[j];
        }
    }

    // ================= single grid barrier: T = max(t_local) =================
    if (tid == 0) {
        atomicMax(&g_T, (unsigned)done_it);
        __threadfence();
        atomicAdd(&g_bar[0], 1u);
        unsigned vv;
        do {
            asm volatile("ld.acquire.gpu.u32 %0, [%1];" : "=r"(vv) : "l"(&g_bar[0]) : "memory");
        } while (vv < (unsigned)NCTA);
        unsigned tg;
        asm volatile("ld.acquire.gpu.u32 %0, [%1];" : "=r"(tg) : "l"(&g_T) : "memory");
        *sRem = tg;
    }
    __syncthreads();
    const int rem = (int)*sRem - done_it;

    // ================= PHASE 2: counted tail, 1 sync/iter =================
#pragma unroll 1
    for (int i = 0; i < rem; ++i) {
        const uint32_t abase = (i & 1) ? aAddr1 : aAddr0;
        const uint32_t sbuf = (i & 1) ? AS1_OFF : AS0_OFF;
#pragma unroll
        for (int mt = 0; mt < 2; ++mt)
#pragma unroll
            for (int nt = 0; nt < 4; ++nt)
#pragma unroll
                for (int ep = 0; ep < 2; ++ep) {
                    unsigned pk = qtanh2(s[mt][nt][ep * 2 + 0], s[mt][nt][ep * 2 + 1]);
                    int row = mt * 16 + r0 + 8 * ep;
                    int col = colBase + nt * 8 + c0;
                    *(unsigned short*)(smem + sbuf + row * WQ_STRIDE + col) = (unsigned short)pk;
                }
        __syncthreads();

        int acc[2][4][4];
#pragma unroll
        for (int mt = 0; mt < 2; ++mt)
#pragma unroll
            for (int nt = 0; nt < 4; ++nt)
#pragma unroll
                for (int e = 0; e < 4; ++e) acc[mt][nt][e] = 0;
#pragma unroll
        for (int ks = 0; ks < 8; ++ks) {
            uint32_t aF[2][4];
#pragma unroll
            for (int mt = 0; mt < 2; ++mt)
                ldsm_x4(abase + (uint32_t)(mt * 16 * WQ_STRIDE) + (uint32_t)(ks * 32),
                        aF[mt][0], aF[mt][1], aF[mt][2], aF[mt][3]);
#pragma unroll
            for (int mt = 0; mt < 2; ++mt)
#pragma unroll
                for (int nt = 0; nt < 4; ++nt)
                    imma(acc[mt][nt], aF[mt],
                         bR[ks][nt >> 1][nt & 1], bR[ks][nt >> 1][(nt & 1) + 2]);
        }
#pragma unroll
        for (int mt = 0; mt < 2; ++mt)
#pragma unroll
            for (int nt = 0; nt < 4; ++nt)
#pragma unroll
                for (int e = 0; e < 4; ++e)
                    s[mt][nt][e] = fmaf(alpha, s[mt][nt][e],
                                        fmaf(betaI, (float)acc[mt][nt][e], cR[mt][nt][e]));
    }

    // ================= epilogue: out = s @ Wop^T + bop =================
    __syncthreads();
    float* wopS = (float*)smem;
    float* partS = (float*)(smem + 10240);
    for (int i = tid; i < NOUT * NH; i += TPB) wopS[i] = Wop[i];
    __syncthreads();
    float part[4][NOUT];
#pragma unroll
    for (int j = 0; j < 4; ++j) {
#pragma unroll
        for (int o = 0; o < NOUT; ++o) part[j][o] = 0.0f;
        int mt = j >> 1, eb = (j & 1) * 2;
#pragma unroll
        for (int nt = 0; nt < 4; ++nt)
#pragma unroll
            for (int b = 0; b < 2; ++b) {
                float sv = s[mt][nt][eb + b];
                int col = colBase + nt * 8 + c0 + b;
#pragma unroll
                for (int o = 0; o < NOUT; ++o)
                    part[j][o] = fmaf(sv, wopS[o * NH + col], part[j][o]);
            }
    }
#pragma unroll
    for (int off = 1; off <= 2; off <<= 1)
#pragma unroll
        for (int j = 0; j < 4; ++j)
#pragma unroll
            for (int o = 0; o < NOUT; ++o)
                part[j][o] += __shfl_xor_sync(0xFFFFFFFFu, part[j][o], off);
    if ((l & 3) == 0) {
#pragma unroll
        for (int j = 0; j < 4; ++j)
#pragma unroll
            for (int o = 0; o < NOUT; ++o)
                partS[((r0 + 8 * j) * NW + w) * NOUT + o] = part[j][o];
    }
    __syncthreads();
    for (int i = tid; i < ROWS * NOUT; i += TPB) {
        int row = i / NOUT, o = i % NOUT;
        float v = bop[o];
#pragma unroll
        for (int ww = 0; ww < NW; ++ww)
            v += partS[(row * NW + ww) * NOUT + o];
        out[(row0 + row) * NOUT + o] = v;
    }
}

// ---------------- launch ----------------
extern "C" void kernel_launch(void* const* d_in, const int* in_sizes, int n_in,
                              void* d_out, int out_size) {
    const float *x = nullptr, *W_ip = nullptr, *b_ip = nullptr, *W_op = nullptr,
                *b_op = nullptr, *W_raw = nullptr, *b_raw = nullptr,
                *a_raw = nullptr, *be_raw = nullptr;
    for (int i = 0; i < n_in; ++i) {
        const float* p = (const float*)d_in[i];
        switch (in_sizes[i]) {
            case NB * NIN:  x = p; break;
            case NH * NIN:  W_ip = p; break;
            case NH * NH:   W_raw = p; break;
            case NOUT * NH: W_op = p; break;
            case NOUT:      b_op = p; break;
            case NH:        if (!b_ip) b_ip = p; else b_raw = p; break;
            case 1:         if (!a_raw) a_raw = p; else be_raw = p; break;
            default: break;
        }
    }

    cudaFuncSetAttribute(k_main, cudaFuncAttributeMaxDynamicSharedMemorySize, SMEM_SZ);

    k_setup<<<2 * NH + 1, 256>>>(W_raw, b_raw, a_raw, be_raw, b_ip, W_ip);
    k_main<<<NCTA, TPB, SMEM_SZ>>>(x, W_op, b_op, (float*)d_out);
}

// round 17
// speedup vs baseline: 1.1221x; 1.0565x over previous
#include <cuda_runtime.h>
#include <cuda_fp16.h>
#include <cstdint>
#include <math.h>

// Problem: B=4096, IN=784, H=256, OUT=10, TOL=1e-3, MAX_ITERS=200
#define NB 4096
#define NIN 784
#define NH 256
#define NOUT 10
#define TOLV 1e-3f
#define MAXIT 200

#define ROWS 32
#define NCTA (NB / ROWS)                 // 128 CTAs <= 148 SMs -> co-resident
#define TPB 256                          // 8 warps
#define NW 8

// ---- iteration-phase SMEM layout (int8) ----
#define WQ_STRIDE 272                    // 256B row + 16B pad
#define AS0_OFF 69632
#define AS1_OFF 78336
#define SW0_OFF 87040
#define SW1_OFF 88064
#define REM_OFF 89088

// ---- xproj SMEM layout (K = 784 = 7 chunks of 112; stride 240B = 15x16, odd) ----
#define KCH 112
#define NCH 7
#define XB_STR 240
#define XBH0 0
#define XBH1 61440
#define XAH0 122880
#define XAL0 130560
#define XAH1 138240
#define XAL1 145920
#define SMEM_SZ 153600

// ---------------- device scratch ----------------
__device__ __align__(16) signed char g_Wq8[NH * NH];  // int8 round(tanh(W)*255)
__device__ float g_ab[2];                             // alpha, beta
__device__ float g_add[NH];                           // b_ip + bq
__device__ __align__(16) __half g_Wh[NIN * NH];       // W_ip fp16, [kc][n][112]
__device__ unsigned g_bar[4];
__device__ unsigned g_T;

// ---------------- helpers ----------------
__device__ __forceinline__ uint32_t smem_u32(const void* p) {
    uint32_t r;
    asm("{ .reg .u64 t; cvta.to.shared.u64 t, %1; cvt.u32.u64 %0, t; }" : "=r"(r) : "l"(p));
    return r;
}
__device__ __forceinline__ float tanh_f32(float x) {
    float t;
    asm("tanh.approx.f32 %0, %1;" : "=f"(t) : "f"(x));
    return t;
}
__device__ __forceinline__ void ldsm_x4(uint32_t a, uint32_t& r0, uint32_t& r1,
                                        uint32_t& r2, uint32_t& r3) {
    asm volatile("ldmatrix.sync.aligned.m8n8.x4.shared.b16 {%0,%1,%2,%3}, [%4];"
                 : "=r"(r0), "=r"(r1), "=r"(r2), "=r"(r3) : "r"(a));
}
__device__ __forceinline__ void hmma(float* c, const uint32_t* a, const uint32_t* b) {
    asm volatile("mma.sync.aligned.m16n8k16.row.col.f32.f16.f16.f32 "
                 "{%0,%1,%2,%3}, {%4,%5,%6,%7}, {%8,%9}, {%0,%1,%2,%3};"
                 : "+f"(c[0]), "+f"(c[1]), "+f"(c[2]), "+f"(c[3])
                 : "r"(a[0]), "r"(a[1]), "r"(a[2]), "r"(a[3]), "r"(b[0]), "r"(b[1]));
}
__device__ __forceinline__ void imma(int* c, const uint32_t* a, uint32_t b0, uint32_t b1) {
    asm volatile("mma.sync.aligned.m16n8k32.row.col.s32.s8.s8.s32 "
                 "{%0,%1,%2,%3}, {%4,%5,%6,%7}, {%8,%9}, {%0,%1,%2,%3};"
                 : "+r"(c[0]), "+r"(c[1]), "+r"(c[2]), "+r"(c[3])
                 : "r"(a[0]), "r"(a[1]), "r"(a[2]), "r"(a[3]), "r"(b0), "r"(b1));
}
__device__ __forceinline__ void cp16(uint32_t dst, const void* src) {
    asm volatile("cp.async.cg.shared.global [%0], [%1], 16;" :: "r"(dst), "l"(src));
}
#define CP_COMMIT() asm volatile("cp.async.commit_group;" ::: "memory")
#define CP_WAIT0()  asm volatile("cp.async.wait_group 0;" ::: "memory")
__device__ __forceinline__ uint32_t pack_h2(__half a, __half b) {
    return (uint32_t)__half_as_ushort(a) | ((uint32_t)__half_as_ushort(b) << 16);
}

// ---------------- K0: fused setup ----------------
__global__ void k_setup(const float* __restrict__ W_raw, const float* __restrict__ b_raw,
                        const float* __restrict__ a_raw, const float* __restrict__ be_raw,
                        const float* __restrict__ b_ip, const float* __restrict__ W_ip) {
    int b = blockIdx.x, t = threadIdx.x;
    if (b < NH) {                                   // Wq row b -> int8
        float w = W_raw[b * NH + t];
        float q = rintf(tanhf(w) * 255.0f);
        q = fminf(fmaxf(q, -127.0f), 127.0f);       // data range is +-2; int8-safe clamp
        g_Wq8[b * NH + t] = (signed char)(int)q;
    } else if (b == NH) {
        float bb = b_raw[t];
        float q = rintf(tanhf(bb) * 255.0f);
        q = fminf(fmaxf(q, -256.0f), 255.0f);
        g_add[t] = b_ip[t] + q / 255.0f;
        if (t < 4) g_bar[t] = 0u;
        if (t == 0) {
            g_T = 0u;
            g_ab[0] = 1.0f / (1.0f + expf(-a_raw[0]));
            g_ab[1] = 1.0f / (1.0f + expf(-be_raw[0]));
        }
    } else {                                        // W_ip row: fp16 hi, chunk-major
        int n = b - NH - 1;
        for (int k2 = t; k2 < NIN / 2; k2 += blockDim.x) {
            int k = 2 * k2;
            __half h0 = __float2half_rn(W_ip[n * NIN + k]);
            __half h1 = __float2half_rn(W_ip[n * NIN + k + 1]);
            int kc = k / KCH, kk = k % KCH;         // pairs never straddle (112 even)
            int dst = kc * (NH * KCH) + n * KCH + kk;
            *(__half2*)&g_Wh[dst] = __halves2half2(h0, h1);
        }
    }
}

// ---------------- K1: fused xproj + two-phase INT8 iteration + output GEMM --------------
__global__ void __launch_bounds__(TPB, 1) k_main(const float* __restrict__ x,
                                                 const float* __restrict__ Wop,
                                                 const float* __restrict__ bop,
                                                 float* __restrict__ out) {
    extern __shared__ char smem[];
    const uint32_t sbase = smem_u32(smem);
    const int tid = threadIdx.x;
    const int w = tid >> 5, l = tid & 31;
    const int r0 = l >> 2, c0 = (l & 3) * 2;
    const int colBase = w * 32;
    const int row0 = blockIdx.x * ROWS;
    unsigned* sRem = (unsigned*)(smem + REM_OFF);

    // ================= xproj: c = (xh+xl) @ Wh^T + add (cp.async double-buffered) =======
    float cR[2][4][4];
#pragma unroll
    for (int mt = 0; mt < 2; ++mt)
#pragma unroll
        for (int nt = 0; nt < 4; ++nt)
#pragma unroll
            for (int e = 0; e < 4; ++e) cR[mt][nt][e] = 0.0f;
    {
        const uint32_t aPiece = (uint32_t)((l & 15) * XB_STR + (l & 16));
        const uint32_t bPiece = (uint32_t)(((l & 7) + ((l & 16) >> 1)) * XB_STR + (l & 8) * 2);
        const int xr = tid >> 3, xk0 = (tid & 7) * 14;    // 8 threads x 14 halves per row
        float2 xv[7];

        // -- prologue: B0 via cp.async, A0 staged directly --
        {
            const char* srcH = (const char*)g_Wh;
#pragma unroll
            for (int j = 0; j < 14; ++j) {                // 3584 16B pieces
                int idx = tid + j * 256;
                int n = idx / 14, p = idx - n * 14;
                cp16(sbase + XBH0 + (uint32_t)(n * XB_STR + p * 16), srcH + idx * 16);
            }
            CP_COMMIT();
#pragma unroll
            for (int p = 0; p < 7; ++p)
                xv[p] = *(const float2*)&x[(row0 + xr) * NIN + xk0 + 2 * p];
            char* pH = smem + XAH0 + xr * XB_STR + xk0 * 2;
            char* pL = smem + XAL0 + xr * XB_STR + xk0 * 2;
#pragma unroll
            for (int p = 0; p < 7; ++p) {
                __half h0 = __float2half_rn(xv[p].x), h1 = __float2half_rn(xv[p].y);
                __half l0 = __float2half_rn(xv[p].x - __half2float(h0));
                __half l1 = __float2half_rn(xv[p].y - __half2float(h1));
                *(uint32_t*)(pH + 4 * p) = pack_h2(h0, h1);
                *(uint32_t*)(pL + 4 * p) = pack_h2(l0, l1);
            }
            CP_WAIT0();
        }

#pragma unroll 1
        for (int kc = 0; kc < NCH; ++kc) {
            __syncthreads();                              // chunk kc visible; old bufs free
            const int cb = kc & 1, nb = (kc + 1) & 1;
            if (kc + 1 < NCH) {
                const char* srcH = (const char*)g_Wh + (kc + 1) * (NH * KCH * 2);
                const uint32_t bh = sbase + (nb ? XBH1 : XBH0);
#pragma unroll
                for (int j = 0; j < 14; ++j) {
                    int idx = tid + j * 256;
                    int n = idx / 14, p = idx - n * 14;
                    cp16(bh + (uint32_t)(n * XB_STR + p * 16), srcH + idx * 16);
                }
                CP_COMMIT();
#pragma unroll
                for (int p = 0; p < 7; ++p)
                    xv[p] = *(const float2*)&x[(row0 + xr) * NIN + (kc + 1) * KCH + xk0 + 2 * p];
            }

            // MMA over chunk kc (7 k16-steps): xh@Wh + xl@Wh
            const uint32_t aH = sbase + (cb ? XAH1 : XAH0) + aPiece;
            const uint32_t aL = sbase + (cb ? XAL1 : XAL0) + aPiece;
            const uint32_t bH = sbase + (cb ? XBH1 : XBH0) + bPiece;
#pragma unroll
            for (int ks = 0; ks < 7; ++ks) {
                const uint32_t kb = (uint32_t)(ks * 32);
                uint32_t aHf[2][4], aLf[2][4], bHf[2][4];
#pragma unroll
                for (int mt = 0; mt < 2; ++mt) {
                    ldsm_x4(aH + (uint32_t)(mt * 16 * XB_STR) + kb,
                            aHf[mt][0], aHf[mt][1], aHf[mt][2], aHf[mt][3]);
                    ldsm_x4(aL + (uint32_t)(mt * 16 * XB_STR) + kb,
                            aLf[mt][0], aLf[mt][1], aLf[mt][2], aLf[mt][3]);
                }
#pragma unroll
                for (int np = 0; np < 2; ++np)
                    ldsm_x4(bH + (uint32_t)((colBase + np * 16) * XB_STR) + kb,
                            bHf[np][0], bHf[np][1], bHf[np][2], bHf[np][3]);
#pragma unroll
                for (int mt = 0; mt < 2; ++mt)
#pragma unroll
                    for (int nt = 0; nt < 4; ++nt) {
                        uint32_t* bh2 = &bHf[nt >> 1][(nt & 1) * 2];
                        hmma(cR[mt][nt], aHf[mt], bh2);
                        hmma(cR[mt][nt], aLf[mt], bh2);
                    }
            }

            if (kc + 1 < NCH) {
                char* pH = smem + (nb ? XAH1 : XAH0) + xr * XB_STR + xk0 * 2;
                char* pL = smem + (nb ? XAL1 : XAL0) + xr * XB_STR + xk0 * 2;
#pragma unroll
                for (int p = 0; p < 7; ++p) {
                    __half h0 = __float2half_rn(xv[p].x), h1 = __float2half_rn(xv[p].y);
                    __half l0 = __float2half_rn(xv[p].x - __half2float(h0));
                    __half l1 = __float2half_rn(xv[p].y - __half2float(h1));
                    *(uint32_t*)(pH + 4 * p) = pack_h2(h0, h1);
                    *(uint32_t*)(pL + 4 * p) = pack_h2(l0, l1);
                }
                CP_WAIT0();
            }
        }
#pragma unroll
        for (int nt = 0; nt < 4; ++nt) {
            int col = colBase + nt * 8 + c0;
            float a0 = g_add[col], a1 = g_add[col + 1];
#pragma unroll
            for (int mt = 0; mt < 2; ++mt)
#pragma unroll
                for (int ep = 0; ep < 2; ++ep) {
                    cR[mt][nt][ep * 2 + 0] += a0;
                    cR[mt][nt][ep * 2 + 1] += a1;
                }
        }
    }
    float s[2][4][4];
#pragma unroll
    for (int mt = 0; mt < 2; ++mt)
#pragma unroll
        for (int nt = 0; nt < 4; ++nt)
#pragma unroll
            for (int e = 0; e < 4; ++e) s[mt][nt][e] = cR[mt][nt][e];

    // ================= stage Wq int8 into padded SMEM =================
    __syncthreads();
    {
        const int4* src = (const int4*)g_Wq8;
        for (int i = tid; i < NH * 16; i += TPB) {
            int n = i >> 4, p = i & 15;
            *(int4*)(smem + n * WQ_STRIDE + p * 16) = src[i];
        }
    }
    const float alpha = g_ab[0];
    const float betaI = g_ab[1] * (1.0f / (255.0f * 127.0f));
    __syncthreads();

    const uint32_t aPieceI = (uint32_t)((l & 15) * WQ_STRIDE + ((l >> 4) * 16));
    const uint32_t aAddr0 = sbase + AS0_OFF + aPieceI;
    const uint32_t aAddr1 = sbase + AS1_OFF + aPieceI;
    const uint32_t bAddrW = sbase + (uint32_t)((colBase + (l & 15)) * WQ_STRIDE + (l >> 4) * 16);

    uint32_t bR[8][2][4];
#pragma unroll
    for (int ks = 0; ks < 8; ++ks)
#pragma unroll
        for (int np = 0; np < 2; ++np)
            ldsm_x4(bAddrW + (uint32_t)(np * 16 * WQ_STRIDE) + (uint32_t)(ks * 32),
                    bR[ks][np][0], bR[ks][np][1], bR[ks][np][2], bR[ks][np][3]);

    // ---- prologue: A(s0) -> buf0 ----
#pragma unroll
    for (int mt = 0; mt < 2; ++mt)
#pragma unroll
        for (int nt = 0; nt < 4; ++nt)
#pragma unroll
            for (int ep = 0; ep < 2; ++ep) {
                int i0 = __float2int_rn(tanh_f32(s[mt][nt][ep * 2 + 0]) * 127.0f);
                int i1 = __float2int_rn(tanh_f32(s[mt][nt][ep * 2 + 1]) * 127.0f);
                unsigned pk = __byte_perm((unsigned)i0, (unsigned)i1, 0x0040);
                int row = mt * 16 + r0 + 8 * ep;
                int col = colBase + nt * 8 + c0;
                *(unsigned short*)(smem + AS0_OFF + row * WQ_STRIDE + col) = (unsigned short)pk;
            }
    __syncthreads();

    unsigned sticky = 0u;
    int done_it = MAXIT;

    // ============ PHASE 1: fused update+A-store, 1 sync/iter, delayed vote ============
#pragma unroll 1
    for (int it = 0; it < MAXIT; ++it) {
        if (it > 0) {                           // vote on update #it (written last body)
            const float* sv = (const float*)(smem + (((it - 1) & 1) ? SW1_OFF : SW0_OFF));
            float m = sv[l];
#pragma unroll
            for (int ww = 1; ww < NW; ++ww)
                m = fmaxf(m, sv[ww * 32 + l]);
            sticky |= __ballot_sync(0xFFFFFFFFu, m < TOLV);
            if (sticky == 0xFFFFFFFFu) { done_it = it; break; }
        }

        // MMA from buf(it&1)
        const uint32_t abase = (it & 1) ? aAddr1 : aAddr0;
        int acc[2][4][4];
#pragma unroll
        for (int mt = 0; mt < 2; ++mt)
#pragma unroll
            for (int nt = 0; nt < 4; ++nt)
#pragma unroll
                for (int e = 0; e < 4; ++e) acc[mt][nt][e] = 0;
#pragma unroll
        for (int ks = 0; ks < 8; ++ks) {
            uint32_t aF[2][4];
#pragma unroll
            for (int mt = 0; mt < 2; ++mt)
                ldsm_x4(abase + (uint32_t)(mt * 16 * WQ_STRIDE) + (uint32_t)(ks * 32),
                        aF[mt][0], aF[mt][1], aF[mt][2], aF[mt][3]);
#pragma unroll
            for (int mt = 0; mt < 2; ++mt)
#pragma unroll
                for (int nt = 0; nt < 4; ++nt)
                    imma(acc[mt][nt], aF[mt],
                         bR[ks][nt >> 1][nt & 1], bR[ks][nt >> 1][(nt & 1) + 2]);
        }

        // fused: update s (update #it+1), dmax, and A(s_new) -> buf((it+1)&1)
        const uint32_t nbuf = ((it + 1) & 1) ? AS1_OFF : AS0_OFF;
        float dmax[4] = {0.0f, 0.0f, 0.0f, 0.0f};
#pragma unroll
        for (int mt = 0; mt < 2; ++mt)
#pragma unroll
            for (int nt = 0; nt < 4; ++nt)
#pragma unroll
                for (int ep = 0; ep < 2; ++ep) {
                    int e0 = ep * 2, e1 = ep * 2 + 1;
                    float sn0 = fmaf(alpha, s[mt][nt][e0],
                                     fmaf(betaI, (float)acc[mt][nt][e0], cR[mt][nt][e0]));
                    float sn1 = fmaf(alpha, s[mt][nt][e1],
                                     fmaf(betaI, (float)acc[mt][nt][e1], cR[mt][nt][e1]));
                    int j = mt * 2 + ep;
                    dmax[j] = fmaxf(dmax[j], fmaxf(fabsf(sn0 - s[mt][nt][e0]),
                                                   fabsf(sn1 - s[mt][nt][e1])));
                    s[mt][nt][e0] = sn0;
                    s[mt][nt][e1] = sn1;
                    int i0 = __float2int_rn(tanh_f32(sn0) * 127.0f);
                    int i1 = __float2int_rn(tanh_f32(sn1) * 127.0f);
                    unsigned pk = __byte_perm((unsigned)i0, (unsigned)i1, 0x0040);
                    int row = mt * 16 + r0 + 8 * ep;
                    int col = colBase + nt * 8 + c0;
                    *(unsigned short*)(smem + nbuf + row * WQ_STRIDE + col) = (unsigned short)pk;
                }
#pragma unroll
        for (int off = 1; off <= 2; off <<= 1)
#pragma unroll
            for (int j = 0; j < 4; ++j)
                dmax[j] = fmaxf(dmax[j], __shfl_xor_sync(0xFFFFFFFFu, dmax[j], off));
        float* sw = (float*)(smem + ((it & 1) ? SW1_OFF : SW0_OFF));
        if ((l & 3) == 0) {
#pragma unroll
            for (int j = 0; j < 4; ++j)
                sw[w * 32 + r0 + 8 * j] = dmax[j];
        }
        __syncthreads();                        // publishes A(next) + sW
    }

    // ================= single grid barrier: T = max(t_local) =================
    if (tid == 0) {
        atomicMax(&g_T, (unsigned)done_it);
        __threadfence();
        atomicAdd(&g_bar[0], 1u);
        unsigned vv;
        do {
            asm volatile("ld.acquire.gpu.u32 %0, [%1];" : "=r"(vv) : "l"(&g_bar[0]) : "memory");
        } while (vv < (unsigned)NCTA);
        unsigned tg;
        asm volatile("ld.acquire.gpu.u32 %0, [%1];" : "=r"(tg) : "l"(&g_T) : "memory");
        *sRem = tg;
    }
    __syncthreads();
    const int rem = (int)*sRem - done_it;

    // ================= PHASE 2: counted tail, fused, 1 sync/iter =================
#pragma unroll 1
    for (int j2 = 0; j2 < rem; ++j2) {
        const int it = done_it + j2;
        const uint32_t abase = (it & 1) ? aAddr1 : aAddr0;
        int acc[2][4][4];
#pragma unroll
        for (int mt = 0; mt < 2; ++mt)
#pragma unroll
            for (int nt = 0; nt < 4; ++nt)
#pragma unroll
                for (int e = 0; e < 4; ++e) acc[mt][nt][e] = 0;
#pragma unroll
        for (int ks = 0; ks < 8; ++ks) {
            uint32_t aF[2][4];
#pragma unroll
            for (int mt = 0; mt < 2; ++mt)
                ldsm_x4(abase + (uint32_t)(mt * 16 * WQ_STRIDE) + (uint32_t)(ks * 32),
                        aF[mt][0], aF[mt][1], aF[mt][2], aF[mt][3]);
#pragma unroll
            for (int mt = 0; mt < 2; ++mt)
#pragma unroll
                for (int nt = 0; nt < 4; ++nt)
                    imma(acc[mt][nt], aF[mt],
                         bR[ks][nt >> 1][nt & 1], bR[ks][nt >> 1][(nt & 1) + 2]);
        }
        const uint32_t nbuf = ((it + 1) & 1) ? AS1_OFF : AS0_OFF;
#pragma unroll
        for (int mt = 0; mt < 2; ++mt)
#pragma unroll
            for (int nt = 0; nt < 4; ++nt)
#pragma unroll
                for (int ep = 0; ep < 2; ++ep) {
                    int e0 = ep * 2, e1 = ep * 2 + 1;
                    float sn0 = fmaf(alpha, s[mt][nt][e0],
                                     fmaf(betaI, (float)acc[mt][nt][e0], cR[mt][nt][e0]));
                    float sn1 = fmaf(alpha, s[mt][nt][e1],
                                     fmaf(betaI, (float)acc[mt][nt][e1], cR[mt][nt][e1]));
                    s[mt][nt][e0] = sn0;
                    s[mt][nt][e1] = sn1;
                    int i0 = __float2int_rn(tanh_f32(sn0) * 127.0f);
                    int i1 = __float2int_rn(tanh_f32(sn1) * 127.0f);
                    unsigned pk = __byte_perm((unsigned)i0, (unsigned)i1, 0x0040);
                    int row = mt * 16 + r0 + 8 * ep;
                    int col = colBase + nt * 8 + c0;
                    *(unsigned short*)(smem + nbuf + row * WQ_STRIDE + col) = (unsigned short)pk;
                }
        __syncthreads();
    }

    // ================= epilogue: out = s @ Wop^T + bop =================
    __syncthreads();
    float* wopS = (float*)smem;
    float* partS = (float*)(smem + 10240);
    for (int i = tid; i < NOUT * NH; i += TPB) wopS[i] = Wop[i];
    __syncthreads();
    float part[4][NOUT];
#pragma unroll
    for (int j = 0; j < 4; ++j) {
#pragma unroll
        for (int o = 0; o < NOUT; ++o) part[j][o] = 0.0f;
        int mt = j >> 1, eb = (j & 1) * 2;
#pragma unroll
        for (int nt = 0; nt < 4; ++nt)
#pragma unroll
            for (int b = 0; b < 2; ++b) {
                float sv = s[mt][nt][eb + b];
                int col = colBase + nt * 8 + c0 + b;
#pragma unroll
                for (int o = 0; o < NOUT; ++o)
                    part[j][o] = fmaf(sv, wopS[o * NH + col], part[j][o]);
            }
    }
#pragma unroll
    for (int off = 1; off <= 2; off <<= 1)
#pragma unroll
        for (int j = 0; j < 4; ++j)
#pragma unroll
            for (int o = 0; o < NOUT; ++o)
                part[j][o] += __shfl_xor_sync(0xFFFFFFFFu, part[j][o], off);
    if ((l & 3) == 0) {
#pragma unroll
        for (int j = 0; j < 4; ++j)
#pragma unroll
            for (int o = 0; o < NOUT; ++o)
                partS[((r0 + 8 * j) * NW + w) * NOUT + o] = part[j][o];
    }
    __syncthreads();
    for (int i = tid; i < ROWS * NOUT; i += TPB) {
        int row = i / NOUT, o = i % NOUT;
        float v = bop[o];
#pragma unroll
        for (int ww = 0; ww < NW; ++ww)
            v += partS[(row * NW + ww) * NOUT + o];
        out[(row0 + row) * NOUT + o] = v;
    }
}

// ---------------- launch ----------------
extern "C" void kernel_launch(void* const* d_in, const int* in_sizes, int n_in,
                              void* d_out, int out_size) {
    const float *x = nullptr, *W_ip = nullptr, *b_ip = nullptr, *W_op = nullptr,
                *b_op = nullptr, *W_raw = nullptr, *b_raw = nullptr,
                *a_raw = nullptr, *be_raw = nullptr;
    for (int i = 0; i < n_in; ++i) {
        const float* p = (const float*)d_in[i];
        switch (in_sizes[i]) {
            case NB * NIN:  x = p; break;
            case NH * NIN:  W_ip = p; break;
            case NH * NH:   W_raw = p; break;
            case NOUT * NH: W_op = p; break;
            case NOUT:      b_op = p; break;
            case NH:        if (!b_ip) b_ip = p; else b_raw = p; break;
            case 1:         if (!a_raw) a_raw = p; else be_raw = p; break;
            default: break;
        }
    }

    cudaFuncSetAttribute(k_main, cudaFuncAttributeMaxDynamicSharedMemorySize, SMEM_SZ);

    k_setup<<<2 * NH + 1, 256>>>(W_raw, b_raw, a_raw, be_raw, b_ip, W_ip);
    k_main<<<NCTA, TPB, SMEM_SZ>>>(x, W_op, b_op, (float*)d_out);
}